// round 9
// baseline (speedup 1.0000x reference)
#include <cuda_runtime.h>
#include <cuda_bf16.h>
#include <cstddef>

#define N_MODELS 63

// HBM-bound streaming kernel at its measured best shape (R8: 78.0us, DRAM
// 83.3%): 4 samples/thread via int4, plain global loads, 256-thread blocks,
// no launch_bounds (47 regs). This round's change: BALANCED PERSISTENT GRID —
// launch exactly (resident blocks/SM * num SMs) blocks so there is no partial
// final wave (1954 tiles / 740 slots = 2.64 waves previously; the 474-block
// tail wave idled ~36% of the chip's DRAM request streams for its duration).
// The grid-stride loop spreads tiles 2-3 per block, imbalance <= 1 iteration.
//
// c1/c0 accumulated SEPARATELY, sequentially over m, exactly mirroring the
// reference's two-sum-then-compare fp semantics. Do NOT reorder the sums:
// one flipped marginal sample = 1e-3 rel_err = fail.
__global__ void vote4_kernel(const int4* __restrict__ votes,
                             const float* __restrict__ weights,
                             float4* __restrict__ out,
                             int n4) {
    __shared__ float sw[N_MODELS];
    if (threadIdx.x < N_MODELS) sw[threadIdx.x] = weights[threadIdx.x];
    __syncthreads();

    int i = blockIdx.x * blockDim.x + threadIdx.x;
    int stride = gridDim.x * blockDim.x;

    for (; i < n4; i += stride) {
        float c1x = 0.f, c1y = 0.f, c1z = 0.f, c1w = 0.f;
        float c0x = 0.f, c0y = 0.f, c0z = 0.f, c0w = 0.f;
#pragma unroll
        for (int m = 0; m < N_MODELS; m++) {
            int4 v = votes[(size_t)m * (size_t)n4 + (size_t)i];
            float wm = sw[m];
            if (v.x) c1x += wm; else c0x += wm;
            if (v.y) c1y += wm; else c0y += wm;
            if (v.z) c1z += wm; else c0z += wm;
            if (v.w) c1w += wm; else c0w += wm;
        }
        float4 o;
        o.x = (c1x > c0x) ? 1.0f : 0.0f;
        o.y = (c1y > c0y) ? 1.0f : 0.0f;
        o.z = (c1z > c0z) ? 1.0f : 0.0f;
        o.w = (c1w > c0w) ? 1.0f : 0.0f;
        out[i] = o;
    }
}

// Scalar tail (never runs for n = 2e6, kept for generality).
__global__ void vote_tail_kernel(const int* __restrict__ votes,
                                 const float* __restrict__ weights,
                                 float* __restrict__ out,
                                 int n, int start) {
    int i = start + blockIdx.x * blockDim.x + threadIdx.x;
    if (i >= n) return;
    float c1 = 0.f, c0 = 0.f;
    for (int m = 0; m < N_MODELS; m++) {
        float wm = weights[m];
        if (votes[(size_t)m * (size_t)n + (size_t)i]) c1 += wm; else c0 += wm;
    }
    out[i] = (c1 > c0) ? 1.0f : 0.0f;
}

extern "C" void kernel_launch(void* const* d_in, const int* in_sizes, int n_in,
                              void* d_out, int out_size) {
    // Bind inputs by SIZE: weights has exactly N_MODELS elements; votes is
    // the big matrix. Derive n from the votes element count.
    const int* votes = nullptr;
    const float* weights = nullptr;
    long long votes_elems = 0;
    for (int k = 0; k < n_in; k++) {
        if (in_sizes[k] == N_MODELS) {
            weights = (const float*)d_in[k];
        } else {
            votes = (const int*)d_in[k];
            votes_elems = in_sizes[k];
        }
    }
    float* out = (float*)d_out;   // float32 0/1 output (established round 4)

    int n = (int)(votes_elems / N_MODELS);   // samples (2e6)
    int n4 = n / 4;
    int tail_start = n4 * 4;

    if (n4 > 0) {
        const int threads = 256;
        int tiles = (n4 + threads - 1) / threads;   // 1954 for n=2e6

        // Balanced persistent grid: exactly one resident wave, computed once
        // (static init is deterministic; queries are alloc-free and
        // capture-safe — they are host calls, not graph nodes).
        static int balanced_blocks = 0;
        if (balanced_blocks == 0) {
            int sms = 0, per_sm = 0;
            if (cudaDeviceGetAttribute(&sms, cudaDevAttrMultiProcessorCount, 0)
                    != cudaSuccess || sms <= 0)
                sms = 148;
            if (cudaOccupancyMaxActiveBlocksPerMultiprocessor(
                    &per_sm, vote4_kernel, threads, sizeof(float) * N_MODELS)
                    != cudaSuccess || per_sm <= 0)
                per_sm = 5;
            balanced_blocks = sms * per_sm;
        }

        int blocks = (tiles < balanced_blocks) ? tiles : balanced_blocks;
        vote4_kernel<<<blocks, threads>>>((const int4*)votes, weights,
                                          (float4*)out, n4);
    }
    if (tail_start < n) {
        int rem = n - tail_start;
        vote_tail_kernel<<<(rem + 127) / 128, 128>>>(votes, weights, out, n,
                                                     tail_start);
    }
}

// round 10
// speedup vs baseline: 1.0254x; 1.0254x over previous
#include <cuda_runtime.h>
#include <cuda_bf16.h>
#include <cstddef>

#define N_MODELS 63

// FINAL (converged) configuration — best measured: R8 @ 78.0us, DRAM 83.3%,
// 6.6TB/s. 4 samples/thread via int4, plain global loads, 256-thread blocks,
// grid = ceil(n4/256) = 1954, no launch_bounds (47 regs, ~5 blocks/SM).
//
// Session evidence for convergence (all same wall-time band 78-81us):
//   R6: __ldcs + occ 72%        -> neutral (cache policy irrelevant, no reuse)
//   R7: 8-wide threads          -> REGRESSED to 92.6us (fewer load streams,
//                                  DRAM 69.6% — stream count is what matters)
//   R9: balanced persistent grid-> neutral (scheduler backfills partial waves)
// Problem is DRAM-scheduler-saturated: 504MB mandatory int32 reads at
// ~6.5TB/s achieved (~82% of 8TB/s spec) = ~78us floor.
//
// c1/c0 accumulated SEPARATELY, sequentially over m, exactly mirroring the
// reference's two-sum-then-compare fp semantics. Do NOT reorder the sums:
// one flipped marginal sample = 1e-3 rel_err = fail (threshold is strict <).
__global__ void vote4_kernel(const int4* __restrict__ votes,
                             const float* __restrict__ weights,
                             float4* __restrict__ out,
                             int n4) {
    __shared__ float sw[N_MODELS];
    if (threadIdx.x < N_MODELS) sw[threadIdx.x] = weights[threadIdx.x];
    __syncthreads();

    int i = blockIdx.x * blockDim.x + threadIdx.x;
    int stride = gridDim.x * blockDim.x;

    for (; i < n4; i += stride) {
        float c1x = 0.f, c1y = 0.f, c1z = 0.f, c1w = 0.f;
        float c0x = 0.f, c0y = 0.f, c0z = 0.f, c0w = 0.f;
#pragma unroll
        for (int m = 0; m < N_MODELS; m++) {
            int4 v = votes[(size_t)m * (size_t)n4 + (size_t)i];
            float wm = sw[m];
            if (v.x) c1x += wm; else c0x += wm;
            if (v.y) c1y += wm; else c0y += wm;
            if (v.z) c1z += wm; else c0z += wm;
            if (v.w) c1w += wm; else c0w += wm;
        }
        float4 o;
        o.x = (c1x > c0x) ? 1.0f : 0.0f;
        o.y = (c1y > c0y) ? 1.0f : 0.0f;
        o.z = (c1z > c0z) ? 1.0f : 0.0f;
        o.w = (c1w > c0w) ? 1.0f : 0.0f;
        out[i] = o;
    }
}

// Scalar tail (never runs for n = 2e6, kept for generality).
__global__ void vote_tail_kernel(const int* __restrict__ votes,
                                 const float* __restrict__ weights,
                                 float* __restrict__ out,
                                 int n, int start) {
    int i = start + blockIdx.x * blockDim.x + threadIdx.x;
    if (i >= n) return;
    float c1 = 0.f, c0 = 0.f;
    for (int m = 0; m < N_MODELS; m++) {
        float wm = weights[m];
        if (votes[(size_t)m * (size_t)n + (size_t)i]) c1 += wm; else c0 += wm;
    }
    out[i] = (c1 > c0) ? 1.0f : 0.0f;
}

extern "C" void kernel_launch(void* const* d_in, const int* in_sizes, int n_in,
                              void* d_out, int out_size) {
    // Bind inputs by SIZE: weights has exactly N_MODELS elements; votes is
    // the big matrix. Derive n from the votes element count.
    const int* votes = nullptr;
    const float* weights = nullptr;
    long long votes_elems = 0;
    for (int k = 0; k < n_in; k++) {
        if (in_sizes[k] == N_MODELS) {
            weights = (const float*)d_in[k];
        } else {
            votes = (const int*)d_in[k];
            votes_elems = in_sizes[k];
        }
    }
    float* out = (float*)d_out;   // float32 0/1 output (established round 4)

    int n = (int)(votes_elems / N_MODELS);   // samples (2e6)
    int n4 = n / 4;
    int tail_start = n4 * 4;

    if (n4 > 0) {
        const int threads = 256;
        int blocks = (n4 + threads - 1) / threads;   // 1954 for n=2e6
        vote4_kernel<<<blocks, threads>>>((const int4*)votes, weights,
                                          (float4*)out, n4);
    }
    if (tail_start < n) {
        int rem = n - tail_start;
        vote_tail_kernel<<<(rem + 127) / 128, 128>>>(votes, weights, out, n,
                                                     tail_start);
    }
}